// round 10
// baseline (speedup 1.0000x reference)
#include <cuda_runtime.h>
#include <cuda_fp16.h>
#include <cstdint>

#define NNETS 76
#define HD    64

__device__ float g_tau[NNETS * 32768];

// ---------------- helpers ----------------
__device__ __forceinline__ unsigned smem_u32(const void* p) {
    unsigned r;
    asm("{ .reg .u64 t; cvta.to.shared.u64 t, %1; cvt.u32.u64 %0, t; }" : "=r"(r) : "l"(p));
    return r;
}
__device__ __forceinline__ unsigned h2u(__half2 h) {
    return *reinterpret_cast<unsigned*>(&h);
}

#define LDSM4(r0, r1, r2, r3, addr)                                           \
    asm volatile("ldmatrix.sync.aligned.m8n8.x4.shared.b16 {%0,%1,%2,%3}, [%4];" \
                 : "=r"(r0), "=r"(r1), "=r"(r2), "=r"(r3) : "r"(addr))

#define MMA(c, a, b0, b1)                                                     \
    asm volatile("mma.sync.aligned.m16n8k16.row.col.f32.f16.f16.f32 "         \
                 "{%0,%1,%2,%3},{%4,%5,%6,%7},{%8,%9},{%0,%1,%2,%3};"         \
                 : "+f"((c)[0]), "+f"((c)[1]), "+f"((c)[2]), "+f"((c)[3])     \
                 : "r"((a)[0]), "r"((a)[1]), "r"((a)[2]), "r"((a)[3]),        \
                   "r"(b0), "r"(b1))

// ---------------------------------------------------------------------------
// MLP kernel: persistent CTAs over flattened (net, 128-row-tile) job list.
// 128 threads = 4 warps; each warp owns 32 rows. Single-pass fp16 mma.
// Per k-block: 4 LDSMs issued up-front, layer-1 FFMA fills the LDS latency,
// then 16 mma. kb loop kept non-unrolled to bound register pressure.
// ---------------------------------------------------------------------------
__global__ void __launch_bounds__(128, 3)
mlp_mma_kernel(const float* __restrict__ t_p, const float* __restrict__ comp,
               const float* __restrict__ W1, const float* __restrict__ b1,
               const float* __restrict__ W2, const float* __restrict__ b2,
               const float* __restrict__ W3, const float* __restrict__ b3,
               int B)
{
    __shared__ __align__(128) unsigned char sW2hi[HD * 128];  // [j][k] fp16, swizzled
    __shared__ __align__(8) float sW1a[HD], sW1b[HD], sB1[HD], sB2[HD], sW3[HD];
    __shared__ float sB3;

    const int tid = threadIdx.x;
    const int w   = tid >> 5;
    const int l   = tid & 31;
    const int g   = l >> 2;     // group id (row within 8)
    const int tig = l & 3;      // thread-in-group

    const unsigned w2hi_u = smem_u32(sW2hi);

    const int TPN = B >> 7;                       // tiles per net
    const long long J = (long long)NNETS * TPN;   // total jobs
    const int C  = gridDim.x;
    const int js = (int)((J * blockIdx.x) / C);
    const int je = (int)((J * (blockIdx.x + 1)) / C);

    int curnet = -1;
    const float* cg = nullptr;
    float* taun = nullptr;
    float b3v = 0.f;

    #pragma unroll 1
    for (int job = js; job < je; ++job) {
        const int net  = job / TPN;
        const int tile = job - net * TPN;

        if (net != curnet) {
            __syncthreads();   // all warps done reading previous net's weights
            const float* W2n = W2 + (size_t)net * HD * HD;   // [k][j]
            for (int i = tid; i < HD * HD; i += 128) {
                int k = i >> 6, j = i & 63;
                unsigned off = (unsigned)(j * 128) + ((((unsigned)(k >> 3)) ^ (j & 7)) << 4)
                             + ((k & 7) << 1);
                *(__half*)(sW2hi + off) = __float2half_rn(W2n[i]);
            }
            const float* W1n = W1 + (size_t)net * 2 * HD;
            if (tid < HD) {
                sW1a[tid] = W1n[tid];
                sW1b[tid] = W1n[HD + tid];
                sB1[tid]  = b1[(size_t)net * HD + tid];
                sB2[tid]  = b2[(size_t)net * HD + tid];
                sW3[tid]  = W3[(size_t)net * HD + tid];
            }
            if (tid == 0) sB3 = b3[net];
            __syncthreads();
            curnet = net;
            const int gi = (net < 29) ? 0 : (net < 42) ? 1 : (net < 51) ? 2
                         : (net < 54) ? 3 : (net < 63) ? 4 : 5;
            cg   = comp + (size_t)gi * B;
            taun = g_tau + (size_t)net * B;
            b3v  = sB3;
        }

        const int tbase = tile * 128;
        const int rloc0 = 32 * w + g;   // local rows: rloc0, +8, +16, +24

        // t_p for my 4 fragment rows
        float2 tp[4];
        #pragma unroll
        for (int i = 0; i < 4; ++i)
            tp[i] = ((const float2*)t_p)[tbase + rloc0 + 8 * i];

        // accumulators init with b2 (c0/c2 at col j0, c1/c3 at col j0+1)
        float acc[2][8][4];
        #pragma unroll
        for (int nb = 0; nb < 8; ++nb) {
            float2 b2v = *(const float2*)&sB2[8 * nb + 2 * tig];
            #pragma unroll
            for (int mb = 0; mb < 2; ++mb) {
                acc[mb][nb][0] = b2v.x; acc[mb][nb][1] = b2v.y;
                acc[mb][nb][2] = b2v.x; acc[mb][nb][3] = b2v.y;
            }
        }

        #pragma unroll 1
        for (int kb = 0; kb < 4; ++kb) {
            // ---- issue all 4 B-fragment loads up front ----
            const unsigned csel = 2 * kb + (l >> 4);
            unsigned bh[4][4];
            #pragma unroll
            for (int np = 0; np < 4; ++np) {
                const unsigned n16 = 16 * np + (((unsigned)(l >> 3) & 1) << 3) + (l & 7);
                const unsigned off = n16 * 128 + ((csel ^ (n16 & 7)) << 4);
                LDSM4(bh[np][0], bh[np][1], bh[np][2], bh[np][3], w2hi_u + off);
            }

            // ---- layer 1 (overlaps LDS latency): A fragments for this kb ----
            const int k0 = 16 * kb + 2 * tig;        // and k0+8
            const float2 wa0 = *(const float2*)&sW1a[k0];
            const float2 wa1 = *(const float2*)&sW1a[k0 + 8];
            const float2 wb0 = *(const float2*)&sW1b[k0];
            const float2 wb1 = *(const float2*)&sW1b[k0 + 8];
            const float2 bb0 = *(const float2*)&sB1[k0];
            const float2 bb1 = *(const float2*)&sB1[k0 + 8];

            unsigned Ahi[2][4];
            #pragma unroll
            for (int i = 0; i < 4; ++i) {
                const float tx = tp[i].x, ty = tp[i].y;
                float h00 = fmaxf(fmaf(tx, wa0.x, fmaf(ty, wb0.x, bb0.x)), 0.f);
                float h01 = fmaxf(fmaf(tx, wa0.y, fmaf(ty, wb0.y, bb0.y)), 0.f);
                float h10 = fmaxf(fmaf(tx, wa1.x, fmaf(ty, wb1.x, bb1.x)), 0.f);
                float h11 = fmaxf(fmaf(tx, wa1.y, fmaf(ty, wb1.y, bb1.y)), 0.f);
                __half2 hh0 = __floats2half2_rn(h00, h01);
                __half2 hh1 = __floats2half2_rn(h10, h11);
                const int mb = i >> 1, sl = i & 1;
                Ahi[mb][sl]     = h2u(hh0);
                Ahi[mb][2 + sl] = h2u(hh1);
            }

            // ---- 16 mma from preloaded fragments ----
            #pragma unroll
            for (int np = 0; np < 4; ++np) {
                #pragma unroll
                for (int mb = 0; mb < 2; ++mb) {
                    MMA(acc[mb][2 * np],     Ahi[mb], bh[np][0], bh[np][2]);
                    MMA(acc[mb][2 * np + 1], Ahi[mb], bh[np][1], bh[np][3]);
                }
            }
        }

        // ---- epilogue: relu, W3 dot, quad reduce, tau store ----
        #pragma unroll
        for (int mb = 0; mb < 2; ++mb) {
            float p0 = 0.f, p1 = 0.f;
            #pragma unroll
            for (int nb = 0; nb < 8; ++nb) {
                float2 w3v = *(const float2*)&sW3[8 * nb + 2 * tig];
                p0 = fmaf(fmaxf(acc[mb][nb][0], 0.f), w3v.x, p0);
                p0 = fmaf(fmaxf(acc[mb][nb][1], 0.f), w3v.y, p0);
                p1 = fmaf(fmaxf(acc[mb][nb][2], 0.f), w3v.x, p1);
                p1 = fmaf(fmaxf(acc[mb][nb][3], 0.f), w3v.y, p1);
            }
            p0 += __shfl_xor_sync(0xffffffffu, p0, 1);
            p0 += __shfl_xor_sync(0xffffffffu, p0, 2);
            p1 += __shfl_xor_sync(0xffffffffu, p1, 1);
            p1 += __shfl_xor_sync(0xffffffffu, p1, 2);
            if (tig == 0) {
                const int r0 = tbase + 32 * w + 16 * mb + g;
                const int r1 = r0 + 8;
                taun[r0] = fmaxf(p0 + b3v, 0.f) * cg[r0];
                taun[r1] = fmaxf(p1 + b3v, 0.f) * cg[r1];
            }
        }
    }
}

// ---------------------------------------------------------------------------
// Kernel B: channel combination. One thread per b; 128-thread blocks
// (256 blocks) so all SMs participate.
// ---------------------------------------------------------------------------
__global__ void __launch_bounds__(128)
combine_kernel(const float* __restrict__ comp,
               const float* __restrict__ null_lw, const float* __restrict__ null_iw,
               const float* __restrict__ W_lw, const float* __restrict__ b_lw,
               const float* __restrict__ W_iw, const float* __restrict__ b_iw,
               float* __restrict__ out, int B)
{
    const int b = blockIdx.x * 128 + threadIdx.x;
    if (b >= B) return;

    float tv[NNETS];
    #pragma unroll
    for (int nn = 0; nn < NNETS; ++nn)
        tv[nn] = g_tau[(size_t)nn * B + b];

    float* outG = out;
    float* outL = out + (size_t)30 * B;
    float* outI = out + (size_t)60 * B;

    float ch[30];
    ch[ 0] = tv[ 0] + tv[29] + tv[42] + tv[51] + tv[54] + tv[63];
    ch[ 1] = tv[ 0] + tv[29] + tv[42] + tv[51] + tv[54] + tv[63];
    ch[ 2] = tv[ 1] + tv[30] + tv[43] + tv[52] + tv[55] + tv[64];
    ch[ 3] = tv[ 2] + tv[31] + tv[44] + tv[53] + tv[56] + tv[65];
    ch[ 4] = tv[ 3] + tv[57];
    ch[ 5] = tv[ 4] + tv[58];
    ch[ 6] = tv[ 5] + tv[45];
    ch[ 7] = tv[ 6] + tv[46];
    ch[ 8] = tv[ 7] + tv[59];
    ch[ 9] = tv[ 8] + tv[60];
    ch[10] = tv[ 9] + tv[47];
    ch[11] = tv[10] + tv[48];
    ch[12] = tv[11] + tv[61];
    ch[13] = tv[12] + tv[62];
    ch[14] = tv[13] + tv[49];
    ch[15] = tv[14] + tv[50];
    ch[16] = tv[15] + tv[66];
    ch[17] = tv[16] + tv[67];
    ch[18] = tv[17] + tv[32] + tv[68];
    ch[19] = tv[18] + tv[33] + tv[69];
    ch[20] = tv[19] + tv[34] + tv[70];
    ch[21] = tv[20] + tv[35] + tv[71];
    ch[22] = tv[21] + tv[36] + tv[72];
    ch[23] = tv[22] + tv[37] + tv[73];
    ch[24] = tv[23];
    ch[25] = tv[24];
    ch[26] = tv[25] + tv[38];
    ch[27] = tv[26] + tv[39];
    ch[28] = tv[27] + tv[40] + tv[74];
    ch[29] = tv[28] + tv[41] + tv[75];

    #pragma unroll
    for (int c = 0; c < 30; ++c)
        outG[(size_t)c * B + b] = ch[c];

    const float c6 = comp[(size_t)6 * B + b];
    const float c7 = comp[(size_t)7 * B + b];
    const float nl = null_lw[b];
    const float ni = null_iw[b];
    #pragma unroll
    for (int c = 0; c < 30; ++c) {
        outL[(size_t)c * B + b] = fmaxf(fmaf(nl, W_lw[c], b_lw[c]), 0.0f) * c6;
        outI[(size_t)c * B + b] = fmaxf(fmaf(ni, W_iw[c], b_iw[c]), 0.0f) * c7;
    }
}

// ---------------------------------------------------------------------------
extern "C" void kernel_launch(void* const* d_in, const int* in_sizes, int n_in,
                              void* d_out, int out_size)
{
    const float* t_p     = (const float*)d_in[0];
    const float* comp    = (const float*)d_in[1];
    const float* null_lw = (const float*)d_in[2];
    const float* null_iw = (const float*)d_in[3];
    const float* W1      = (const float*)d_in[4];
    const float* b1      = (const float*)d_in[5];
    const float* W2      = (const float*)d_in[6];
    const float* b2      = (const float*)d_in[7];
    const float* W3      = (const float*)d_in[8];
    const float* b3      = (const float*)d_in[9];
    const float* W_lw    = (const float*)d_in[10];
    const float* b_lw    = (const float*)d_in[11];
    const float* W_iw    = (const float*)d_in[12];
    const float* b_iw    = (const float*)d_in[13];

    const int B = in_sizes[0] / 2;   // t_p is [B, 2]

    mlp_mma_kernel<<<444, 128>>>(t_p, comp, W1, b1, W2, b2, W3, b3, B);

    combine_kernel<<<(B + 127) / 128, 128>>>(comp, null_lw, null_iw,
                                             W_lw, b_lw, W_iw, b_iw,
                                             (float*)d_out, B);
}

// round 11
// speedup vs baseline: 1.5499x; 1.5499x over previous
#include <cuda_runtime.h>
#include <cuda_fp16.h>
#include <cstdint>

#define NNETS 76
#define HD    64

__device__ float g_tau[NNETS * 32768];

// ---------------- helpers ----------------
__device__ __forceinline__ unsigned smem_u32(const void* p) {
    unsigned r;
    asm("{ .reg .u64 t; cvta.to.shared.u64 t, %1; cvt.u32.u64 %0, t; }" : "=r"(r) : "l"(p));
    return r;
}
__device__ __forceinline__ unsigned h2u(__half2 h) {
    return *reinterpret_cast<unsigned*>(&h);
}

#define LDSM4(r0, r1, r2, r3, addr)                                           \
    asm volatile("ldmatrix.sync.aligned.m8n8.x4.shared.b16 {%0,%1,%2,%3}, [%4];" \
                 : "=r"(r0), "=r"(r1), "=r"(r2), "=r"(r3) : "r"(addr))

#define MMA(c, a, b0, b1)                                                     \
    asm volatile("mma.sync.aligned.m16n8k16.row.col.f32.f16.f16.f32 "         \
                 "{%0,%1,%2,%3},{%4,%5,%6,%7},{%8,%9},{%0,%1,%2,%3};"         \
                 : "+f"((c)[0]), "+f"((c)[1]), "+f"((c)[2]), "+f"((c)[3])     \
                 : "r"((a)[0]), "r"((a)[1]), "r"((a)[2]), "r"((a)[3]),        \
                   "r"(b0), "r"(b1))

// ---------------------------------------------------------------------------
// MLP kernel: persistent CTAs over flattened (net, 128-row-tile) job list.
// 128 threads = 4 warps; each warp owns 32 rows. Single-pass fp16 mma.
// (Exact R7 structure — register allocation sits at a cliff; do not add
// live state across the mma stream.)
// ---------------------------------------------------------------------------
__global__ void __launch_bounds__(128, 3)
mlp_mma_kernel(const float* __restrict__ t_p, const float* __restrict__ comp,
               const float* __restrict__ W1, const float* __restrict__ b1,
               const float* __restrict__ W2, const float* __restrict__ b2,
               const float* __restrict__ W3, const float* __restrict__ b3,
               int B)
{
    __shared__ __align__(128) unsigned char sW2hi[HD * 128];  // [j][k] fp16, swizzled
    __shared__ __align__(8) float sW1a[HD], sW1b[HD], sB1[HD], sB2[HD], sW3[HD];
    __shared__ float sB3;

    const int tid = threadIdx.x;
    const int w   = tid >> 5;
    const int l   = tid & 31;
    const int g   = l >> 2;     // group id (row within 8)
    const int tig = l & 3;      // thread-in-group

    const unsigned w2hi_u = smem_u32(sW2hi);

    const int TPN = B >> 7;                       // tiles per net
    const long long J = (long long)NNETS * TPN;   // total jobs
    const int C  = gridDim.x;
    const int js = (int)((J * blockIdx.x) / C);
    const int je = (int)((J * (blockIdx.x + 1)) / C);

    int curnet = -1;
    const float* cg = nullptr;
    float* taun = nullptr;
    float b3v = 0.f;

    #pragma unroll 1
    for (int job = js; job < je; ++job) {
        const int net  = job / TPN;
        const int tile = job - net * TPN;

        if (net != curnet) {
            __syncthreads();   // all warps done reading previous net's weights
            const float* W2n = W2 + (size_t)net * HD * HD;   // [k][j]
            for (int i = tid; i < HD * HD; i += 128) {
                int k = i >> 6, j = i & 63;
                unsigned off = (unsigned)(j * 128) + ((((unsigned)(k >> 3)) ^ (j & 7)) << 4)
                             + ((k & 7) << 1);
                *(__half*)(sW2hi + off) = __float2half_rn(W2n[i]);
            }
            const float* W1n = W1 + (size_t)net * 2 * HD;
            if (tid < HD) {
                sW1a[tid] = W1n[tid];
                sW1b[tid] = W1n[HD + tid];
                sB1[tid]  = b1[(size_t)net * HD + tid];
                sB2[tid]  = b2[(size_t)net * HD + tid];
                sW3[tid]  = W3[(size_t)net * HD + tid];
            }
            if (tid == 0) sB3 = b3[net];
            __syncthreads();
            curnet = net;
            const int gi = (net < 29) ? 0 : (net < 42) ? 1 : (net < 51) ? 2
                         : (net < 54) ? 3 : (net < 63) ? 4 : 5;
            cg   = comp + (size_t)gi * B;
            taun = g_tau + (size_t)net * B;
            b3v  = sB3;
        }

        const int tbase = tile * 128;
        const int rloc0 = 32 * w + g;   // local rows: rloc0, +8, +16, +24

        // t_p for my 4 fragment rows
        float2 tp[4];
        #pragma unroll
        for (int i = 0; i < 4; ++i)
            tp[i] = ((const float2*)t_p)[tbase + rloc0 + 8 * i];

        // accumulators init with b2 (c0/c2 at col j0, c1/c3 at col j0+1)
        float acc[2][8][4];
        #pragma unroll
        for (int nb = 0; nb < 8; ++nb) {
            float2 b2v = *(const float2*)&sB2[8 * nb + 2 * tig];
            #pragma unroll
            for (int mb = 0; mb < 2; ++mb) {
                acc[mb][nb][0] = b2v.x; acc[mb][nb][1] = b2v.y;
                acc[mb][nb][2] = b2v.x; acc[mb][nb][3] = b2v.y;
            }
        }

        #pragma unroll 1
        for (int kb = 0; kb < 4; ++kb) {
            // ---- layer 1: my A-fragment elements for this k-block ----
            const int k0 = 16 * kb + 2 * tig;        // and k0+8
            const float2 wa0 = *(const float2*)&sW1a[k0];
            const float2 wa1 = *(const float2*)&sW1a[k0 + 8];
            const float2 wb0 = *(const float2*)&sW1b[k0];
            const float2 wb1 = *(const float2*)&sW1b[k0 + 8];
            const float2 bb0 = *(const float2*)&sB1[k0];
            const float2 bb1 = *(const float2*)&sB1[k0 + 8];

            unsigned Ahi[2][4];
            #pragma unroll
            for (int i = 0; i < 4; ++i) {
                const float tx = tp[i].x, ty = tp[i].y;
                float h00 = fmaxf(fmaf(tx, wa0.x, fmaf(ty, wb0.x, bb0.x)), 0.f);
                float h01 = fmaxf(fmaf(tx, wa0.y, fmaf(ty, wb0.y, bb0.y)), 0.f);
                float h10 = fmaxf(fmaf(tx, wa1.x, fmaf(ty, wb1.x, bb1.x)), 0.f);
                float h11 = fmaxf(fmaf(tx, wa1.y, fmaf(ty, wb1.y, bb1.y)), 0.f);
                __half2 hh0 = __floats2half2_rn(h00, h01);
                __half2 hh1 = __floats2half2_rn(h10, h11);
                const int mb = i >> 1, sl = i & 1;
                Ahi[mb][sl]     = h2u(hh0);
                Ahi[mb][2 + sl] = h2u(hh1);
            }

            // ---- B fragments + mma (single precision pass) ----
            const unsigned csel = 2 * kb + (l >> 4);
            #pragma unroll
            for (int np = 0; np < 4; ++np) {
                const unsigned n16 = 16 * np + (((unsigned)(l >> 3) & 1) << 3) + (l & 7);
                const unsigned off = n16 * 128 + ((csel ^ (n16 & 7)) << 4);
                unsigned bh0, bh1, bh2, bh3;
                LDSM4(bh0, bh1, bh2, bh3, w2hi_u + off);
                #pragma unroll
                for (int mb = 0; mb < 2; ++mb) {
                    MMA(acc[mb][2 * np],     Ahi[mb], bh0, bh2);
                    MMA(acc[mb][2 * np + 1], Ahi[mb], bh1, bh3);
                }
            }
        }

        // ---- epilogue: relu, W3 dot, quad reduce, tau store ----
        #pragma unroll
        for (int mb = 0; mb < 2; ++mb) {
            float p0 = 0.f, p1 = 0.f;
            #pragma unroll
            for (int nb = 0; nb < 8; ++nb) {
                float2 w3v = *(const float2*)&sW3[8 * nb + 2 * tig];
                p0 = fmaf(fmaxf(acc[mb][nb][0], 0.f), w3v.x, p0);
                p0 = fmaf(fmaxf(acc[mb][nb][1], 0.f), w3v.y, p0);
                p1 = fmaf(fmaxf(acc[mb][nb][2], 0.f), w3v.x, p1);
                p1 = fmaf(fmaxf(acc[mb][nb][3], 0.f), w3v.y, p1);
            }
            p0 += __shfl_xor_sync(0xffffffffu, p0, 1);
            p0 += __shfl_xor_sync(0xffffffffu, p0, 2);
            p1 += __shfl_xor_sync(0xffffffffu, p1, 1);
            p1 += __shfl_xor_sync(0xffffffffu, p1, 2);
            if (tig == 0) {
                const int r0 = tbase + 32 * w + 16 * mb + g;
                const int r1 = r0 + 8;
                taun[r0] = fmaxf(p0 + b3v, 0.f) * cg[r0];
                taun[r1] = fmaxf(p1 + b3v, 0.f) * cg[r1];
            }
        }
    }
}

// ---------------------------------------------------------------------------
// Kernel B: combine. grid = (B/256, 3). Section 0: gas channels with inline
// literal-index sums (no tv[] register array). Sections 1/2: lw / iw.
// ---------------------------------------------------------------------------
__global__ void __launch_bounds__(256)
combine_kernel(const float* __restrict__ comp,
               const float* __restrict__ null_lw, const float* __restrict__ null_iw,
               const float* __restrict__ W_lw, const float* __restrict__ b_lw,
               const float* __restrict__ W_iw, const float* __restrict__ b_iw,
               float* __restrict__ out, int B)
{
    const int b = blockIdx.x * 256 + threadIdx.x;
    if (b >= B) return;
    const int sec = blockIdx.y;

    if (sec == 0) {
        #define T(n) g_tau[(size_t)(n) * B + b]
        #define OC(c, v) out[(size_t)(c) * B + b] = (v)
        const float s01 = T(0) + T(29) + T(42) + T(51) + T(54) + T(63);
        OC(0, s01);
        OC(1, s01);
        OC(2,  T(1) + T(30) + T(43) + T(52) + T(55) + T(64));
        OC(3,  T(2) + T(31) + T(44) + T(53) + T(56) + T(65));
        OC(4,  T(3) + T(57));
        OC(5,  T(4) + T(58));
        OC(6,  T(5) + T(45));
        OC(7,  T(6) + T(46));
        OC(8,  T(7) + T(59));
        OC(9,  T(8) + T(60));
        OC(10, T(9) + T(47));
        OC(11, T(10) + T(48));
        OC(12, T(11) + T(61));
        OC(13, T(12) + T(62));
        OC(14, T(13) + T(49));
        OC(15, T(14) + T(50));
        OC(16, T(15) + T(66));
        OC(17, T(16) + T(67));
        OC(18, T(17) + T(32) + T(68));
        OC(19, T(18) + T(33) + T(69));
        OC(20, T(19) + T(34) + T(70));
        OC(21, T(20) + T(35) + T(71));
        OC(22, T(21) + T(36) + T(72));
        OC(23, T(22) + T(37) + T(73));
        OC(24, T(23));
        OC(25, T(24));
        OC(26, T(25) + T(38));
        OC(27, T(26) + T(39));
        OC(28, T(27) + T(40) + T(74));
        OC(29, T(28) + T(41) + T(75));
        #undef T
        #undef OC
    } else if (sec == 1) {
        const float c6 = comp[(size_t)6 * B + b];
        const float nl = null_lw[b];
        float* outL = out + (size_t)30 * B;
        #pragma unroll
        for (int c = 0; c < 30; ++c)
            outL[(size_t)c * B + b] = fmaxf(fmaf(nl, W_lw[c], b_lw[c]), 0.0f) * c6;
    } else {
        const float c7 = comp[(size_t)7 * B + b];
        const float ni = null_iw[b];
        float* outI = out + (size_t)60 * B;
        #pragma unroll
        for (int c = 0; c < 30; ++c)
            outI[(size_t)c * B + b] = fmaxf(fmaf(ni, W_iw[c], b_iw[c]), 0.0f) * c7;
    }
}

// ---------------------------------------------------------------------------
extern "C" void kernel_launch(void* const* d_in, const int* in_sizes, int n_in,
                              void* d_out, int out_size)
{
    const float* t_p     = (const float*)d_in[0];
    const float* comp    = (const float*)d_in[1];
    const float* null_lw = (const float*)d_in[2];
    const float* null_iw = (const float*)d_in[3];
    const float* W1      = (const float*)d_in[4];
    const float* b1      = (const float*)d_in[5];
    const float* W2      = (const float*)d_in[6];
    const float* b2      = (const float*)d_in[7];
    const float* W3      = (const float*)d_in[8];
    const float* b3      = (const float*)d_in[9];
    const float* W_lw    = (const float*)d_in[10];
    const float* b_lw    = (const float*)d_in[11];
    const float* W_iw    = (const float*)d_in[12];
    const float* b_iw    = (const float*)d_in[13];

    const int B = in_sizes[0] / 2;   // t_p is [B, 2]

    mlp_mma_kernel<<<444, 128>>>(t_p, comp, W1, b1, W2, b2, W3, b3, B);

    dim3 gridC((B + 255) / 256, 3);
    combine_kernel<<<gridC, 256>>>(comp, null_lw, null_iw,
                                   W_lw, b_lw, W_iw, b_iw,
                                   (float*)d_out, B);
}